// round 11
// baseline (speedup 1.0000x reference)
#include <cuda_runtime.h>
#include <cuda_fp16.h>
#include <math.h>

#define E_NUM   600000
#define NRAD    6
#define HID     128
#define NNODES  50000
#define NT      782          // 64-node MLP tiles

__device__ float g_hacc[(size_t)NNODES * HID];
__device__ __align__(256) __half g_wimg[14 * 16384];   // fp16 W^T swizzled chunk images
__device__ int g_cnt[NNODES];        // BSS-zero; re-zeroed by scan each call
__device__ int g_off[NNODES + 1];
__device__ int g_cur[NNODES];
__device__ int g_perm[E_NUM];

// ---------------- helpers ----------------
__device__ __forceinline__ void cpa16(void* dst, const void* src) {
    unsigned d = (unsigned)__cvta_generic_to_shared(dst);
    asm volatile("cp.async.cg.shared.global [%0], [%1], 16;" :: "r"(d), "l"(src));
}
#define CP_COMMIT() asm volatile("cp.async.commit_group;" ::: "memory")
#define CP_WAIT1()  asm volatile("cp.async.wait_group 1;" ::: "memory")
#define CP_WAIT0()  asm volatile("cp.async.wait_group 0;" ::: "memory")

__device__ __forceinline__ void mma16816(float* c, const unsigned* a, unsigned b0, unsigned b1) {
    asm volatile("mma.sync.aligned.m16n8k16.row.col.f32.f16.f16.f32 "
                 "{%0,%1,%2,%3}, {%4,%5,%6,%7}, {%8,%9}, {%0,%1,%2,%3};"
                 : "+f"(c[0]), "+f"(c[1]), "+f"(c[2]), "+f"(c[3])
                 : "r"(a[0]), "r"(a[1]), "r"(a[2]), "r"(a[3]), "r"(b0), "r"(b1));
}
__device__ __forceinline__ unsigned packh2(float x, float y) {
    __half2 h = __floats2half2_rn(x, y);
    return *(unsigned*)&h;
}
__device__ __forceinline__ float silu_f(float v) { return v * (1.0f/(1.0f+__expf(-v))); }

__device__ __forceinline__ int act_off(int m, int k) {
    return m*512 + ((((k>>3) ^ (m&7)) << 4) + (k&7)*2);
}
__device__ __forceinline__ int b_off(int n, int kc) {
    return n*128 + ((((kc>>3) ^ (n&7)) << 4) + (kc&7)*2);
}

// ---------------- CSR build ----------------
__global__ void __launch_bounds__(256) hist_kernel(const void* __restrict__ idx) {
    __shared__ int s64;
    if (threadIdx.x == 0) {
        int a = 1; const int* p = (const int*)idx;
        for (int k = 1; k < 64; k += 2) a &= (p[k] == 0);
        s64 = a;
    }
    __syncthreads();
    const int is64 = s64;
    int stride = gridDim.x * blockDim.x;
    for (int e = blockIdx.x*blockDim.x + threadIdx.x; e < E_NUM; e += stride) {
        int node = is64 ? (int)__ldcs((const long long*)idx + e) : __ldcs((const int*)idx + e);
        atomicAdd(&g_cnt[node], 1);
    }
}

__global__ void __launch_bounds__(1024) scan_kernel() {
    __shared__ int part[1024];
    const int tid = threadIdx.x;
    const int PER = (NNODES + 1023) / 1024;           // 49
    const int base = tid * PER;
    int s = 0;
#pragma unroll 7
    for (int j = 0; j < PER; j++) {
        int i = base + j;
        if (i < NNODES) s += g_cnt[i];
    }
    part[tid] = s;
    __syncthreads();
    for (int off = 1; off < 1024; off <<= 1) {
        int v = (tid >= off) ? part[tid - off] : 0;
        __syncthreads();
        part[tid] += v;
        __syncthreads();
    }
    int run = part[tid] - s;                          // exclusive prefix
    for (int j = 0; j < PER; j++) {
        int i = base + j;
        if (i < NNODES) {
            g_off[i] = run; g_cur[i] = run;
            run += g_cnt[i];
            g_cnt[i] = 0;                             // re-zero for next call
        }
    }
    if (tid == 1023) g_off[NNODES] = run;
}

__global__ void __launch_bounds__(256) scatter_kernel(const void* __restrict__ idx) {
    __shared__ int s64;
    if (threadIdx.x == 0) {
        int a = 1; const int* p = (const int*)idx;
        for (int k = 1; k < 64; k += 2) a &= (p[k] == 0);
        s64 = a;
    }
    __syncthreads();
    const int is64 = s64;
    int stride = gridDim.x * blockDim.x;
    for (int e = blockIdx.x*blockDim.x + threadIdx.x; e < E_NUM; e += stride) {
        int node = is64 ? (int)__ldcs((const long long*)idx + e) : __ldcs((const int*)idx + e);
        int pos = atomicAdd(&g_cur[node], 1);
        g_perm[pos] = e;
    }
}

// ---------------- gather: warp per node, no atomics, hacc written once ----
__global__ void __launch_bounds__(256) gather_kernel(
    const float* __restrict__ x, const float* __restrict__ rbf,
    const float* __restrict__ Wr)
{
    __shared__ float Wsh[NRAD * HID];
    for (int t = threadIdx.x; t < NRAD*HID; t += blockDim.x) Wsh[t] = Wr[t];
    __syncthreads();
    const int node = blockIdx.x * 8 + (threadIdx.x >> 5);
    if (node >= NNODES) return;
    const int c = (threadIdx.x & 31) * 4;
    const int beg = __ldg(&g_off[node]);
    const int end = __ldg(&g_off[node + 1]);
    const float* W0 = Wsh + c;
    float a0 = 0.f, a1 = 0.f, a2 = 0.f, a3 = 0.f;
    for (int p = beg; p < end; p++) {
        int e = __ldcs(&g_perm[p]);
        const float2* rp2 = (const float2*)(rbf + (size_t)e * NRAD);
        float2 q0 = __ldcs(rp2), q1 = __ldcs(rp2 + 1), q2 = __ldcs(rp2 + 2);
        float4 xv = __ldcs((const float4*)(x + (size_t)e*HID + c));
        float w0 = q0.x*W0[0]+q0.y*W0[HID]+q1.x*W0[2*HID]+q1.y*W0[3*HID]+q2.x*W0[4*HID]+q2.y*W0[5*HID];
        float w1 = q0.x*W0[1]+q0.y*W0[HID+1]+q1.x*W0[2*HID+1]+q1.y*W0[3*HID+1]+q2.x*W0[4*HID+1]+q2.y*W0[5*HID+1];
        float w2 = q0.x*W0[2]+q0.y*W0[HID+2]+q1.x*W0[2*HID+2]+q1.y*W0[3*HID+2]+q2.x*W0[4*HID+2]+q2.y*W0[5*HID+2];
        float w3 = q0.x*W0[3]+q0.y*W0[HID+3]+q1.x*W0[2*HID+3]+q1.y*W0[3*HID+3]+q2.x*W0[4*HID+3]+q2.y*W0[5*HID+3];
        a0 += w0*xv.x; a1 += w1*xv.y; a2 += w2*xv.z; a3 += w3*xv.w;
    }
    *(float4*)(g_hacc + (size_t)node*HID + c) = make_float4(a0, a1, a2, a3);
}

// ---------------- prep: fp16 W^T swizzled chunk images ----------------
__global__ void __launch_bounds__(256) prep_kernel(const float* __restrict__ Wd,
                                                   const float* __restrict__ Ws)
{
    size_t stride = (size_t)gridDim.x * blockDim.x;
    for (size_t e = (size_t)blockIdx.x*blockDim.x + threadIdx.x; e < 229376; e += stride) {
        int l, k, n;
        if (e < 32768) { l = 0; k = (int)(e >> 8); n = (int)(e & 255); }
        else { size_t r = e - 32768; l = 1 + (int)(r >> 16); k = (int)((r >> 8) & 255); n = (int)(r & 255); }
        float w = (l == 0) ? Wd[k*256+n] : Ws[(size_t)(l-1)*65536 + k*256 + n];
        int chunk = k >> 6, kc = k & 63;
        int tile = (l == 0) ? chunk : 2 + (l-1)*4 + chunk;
        int dst = n*64 + (((kc>>3) ^ (n&7)) << 3) + (kc&7);
        g_wimg[(size_t)tile*16384 + dst] = __float2half_rn(w);
    }
}

// ---------------- MLP on mma.sync fp16 (round-8 form) ----------------
#define SMEM_DYN (32768 + 2*32768)

__global__ void __launch_bounds__(256, 2) mlp_kernel(const float* __restrict__ bs,
                                                     float* __restrict__ out)
{
    extern __shared__ char dsm[];
    char* act = dsm;
    char* bbuf[2] = { dsm + 32768, dsm + 65536 };

    const int tid  = threadIdx.x;
    const int wid  = tid >> 5, lane = tid & 31;
    const int wm   = wid >> 2;
    const int wn   = wid & 3;
    const int gr   = lane >> 2;
    const int gc   = lane & 3;
    const int nodeBase = blockIdx.x * 64;

    {
        int row = tid >> 2;
        int q   = tid & 3;
        int node = nodeBase + row;
        bool ok  = (node < NNODES);
        const float4* src = (const float4*)(g_hacc + (size_t)node * HID);
#pragma unroll
        for (int w4 = 0; w4 < 8; w4++) {
            int k0 = q*32 + w4*4;
            float4 v = ok ? __ldcs(&src[k0 >> 2]) : make_float4(0.f,0.f,0.f,0.f);
            *(unsigned*)(act + act_off(row, k0))     = packh2(v.x, v.y);
            *(unsigned*)(act + act_off(row, k0 + 2)) = packh2(v.z, v.w);
        }
    }
    __syncthreads();

    for (int l = 0; l < 4; l++) {
        const int nch   = (l == 0) ? 2 : 4;
        const int tbase = (l == 0) ? 0 : 2 + (l-1)*4;

        float C[2][8][4];
#pragma unroll
        for (int i=0;i<2;i++)
#pragma unroll
            for (int j=0;j<8;j++) { C[i][j][0]=0.f; C[i][j][1]=0.f; C[i][j][2]=0.f; C[i][j][3]=0.f; }

        {
            const char* src = (const char*)(g_wimg + (size_t)tbase*16384) + tid*16;
#pragma unroll
            for (int q = 0; q < 8; q++) cpa16(bbuf[0] + tid*16 + q*4096, src + q*4096);
            CP_COMMIT();
        }

        for (int c = 0; c < nch; c++) {
            const int b = c & 1;
            if (c + 1 < nch) {
                const char* src = (const char*)(g_wimg + (size_t)(tbase+c+1)*16384) + tid*16;
#pragma unroll
                for (int q = 0; q < 8; q++) cpa16(bbuf[b^1] + tid*16 + q*4096, src + q*4096);
                CP_COMMIT();
                CP_WAIT1();
            } else CP_WAIT0();
            __syncthreads();

            const char* bb = bbuf[b];
#pragma unroll
            for (int kk = 0; kk < 4; kk++) {
                const int kb = c*64 + kk*16;
                const int kc = kk*16;
                unsigned a[2][4];
#pragma unroll
                for (int i = 0; i < 2; i++) {
                    int m = wm*32 + i*16 + gr;
                    a[i][0] = *(const unsigned*)(act + act_off(m,     kb     + gc*2));
                    a[i][1] = *(const unsigned*)(act + act_off(m + 8, kb     + gc*2));
                    a[i][2] = *(const unsigned*)(act + act_off(m,     kb + 8 + gc*2));
                    a[i][3] = *(const unsigned*)(act + act_off(m + 8, kb + 8 + gc*2));
                }
#pragma unroll
                for (int j = 0; j < 8; j++) {
                    int n = wn*64 + j*8 + gr;
                    unsigned b0 = *(const unsigned*)(bb + b_off(n, kc     + gc*2));
                    unsigned b1 = *(const unsigned*)(bb + b_off(n, kc + 8 + gc*2));
#pragma unroll
                    for (int i = 0; i < 2; i++) mma16816(C[i][j], a[i], b0, b1);
                }
            }
            __syncthreads();
        }

        if (l < 3) {
#pragma unroll
            for (int i = 0; i < 2; i++) {
                int r0 = wm*32 + i*16 + gr;
#pragma unroll
                for (int j = 0; j < 8; j++) {
                    int n0 = wn*64 + j*8 + gc*2;
                    float v00=C[i][j][0], v01=C[i][j][1], v10=C[i][j][2], v11=C[i][j][3];
                    if (l > 0) {
                        float b0 = __ldg(bs + (l-1)*256 + n0), b1 = __ldg(bs + (l-1)*256 + n0 + 1);
                        v00 = silu_f(v00 + b0); v01 = silu_f(v01 + b1);
                        v10 = silu_f(v10 + b0); v11 = silu_f(v11 + b1);
                    }
                    *(unsigned*)(act + act_off(r0,     n0)) = packh2(v00, v01);
                    *(unsigned*)(act + act_off(r0 + 8, n0)) = packh2(v10, v11);
                }
            }
            __syncthreads();
        } else {
#pragma unroll
            for (int i = 0; i < 2; i++) {
                int r0 = wm*32 + i*16 + gr;
                long long node0 = nodeBase + r0, node1 = node0 + 8;
#pragma unroll
                for (int j = 0; j < 8; j++) {
                    int n0 = wn*64 + j*8 + gc*2;
                    float b0 = __ldg(bs + 512 + n0), b1 = __ldg(bs + 512 + n0 + 1);
                    if (node0 < NNODES) {
                        float* op = out + (size_t)node0*256 + n0;
                        op[0] = silu_f(C[i][j][0] + b0);
                        op[1] = silu_f(C[i][j][1] + b1);
                    }
                    if (node1 < NNODES) {
                        float* op = out + (size_t)node1*256 + n0;
                        op[0] = silu_f(C[i][j][2] + b0);
                        op[1] = silu_f(C[i][j][3] + b1);
                    }
                }
            }
        }
    }
}

// ---------------------------------------------------------------------------
extern "C" void kernel_launch(void* const* d_in, const int* in_sizes, int n_in,
                              void* d_out, int out_size)
{
    const float* x      = (const float*)d_in[0];
    const float* rbf    = (const float*)d_in[1];
    const void*  idx    = d_in[2];
    const float* W_rbf  = (const float*)d_in[3];
    const float* W_down = (const float*)d_in[4];
    const float* Ws     = (const float*)d_in[5];
    const float* bs     = (const float*)d_in[6];
    float* out = (float*)d_out;

    hist_kernel<<<1184, 256>>>(idx);
    prep_kernel<<<224, 256>>>(W_down, Ws);
    scan_kernel<<<1, 1024>>>();
    scatter_kernel<<<1184, 256>>>(idx);
    gather_kernel<<<6250, 256>>>(x, rbf, W_rbf);
    cudaFuncSetAttribute(mlp_kernel, cudaFuncAttributeMaxDynamicSharedMemorySize, SMEM_DYN);
    mlp_kernel<<<NT, 256, SMEM_DYN>>>(bs, out);
}

// round 13
// speedup vs baseline: 1.3931x; 1.3931x over previous
#include <cuda_runtime.h>
#include <cuda_fp16.h>
#include <math.h>

#define E_NUM   600000
#define NRAD    6
#define HID     128
#define NNODES  50000
#define NT      782          // 64-node MLP tiles

__device__ float g_hacc[(size_t)NNODES * HID];
__device__ __align__(256) __half g_wimg[14 * 16384];   // fp16 W^T swizzled chunk images

// ---------------- helpers ----------------
__device__ __forceinline__ void cpa16(void* dst, const void* src) {
    unsigned d = (unsigned)__cvta_generic_to_shared(dst);
    asm volatile("cp.async.cg.shared.global [%0], [%1], 16;" :: "r"(d), "l"(src));
}
#define CP_COMMIT() asm volatile("cp.async.commit_group;" ::: "memory")
#define CP_WAIT1()  asm volatile("cp.async.wait_group 1;" ::: "memory")
#define CP_WAIT0()  asm volatile("cp.async.wait_group 0;" ::: "memory")

__device__ __forceinline__ void mma16816(float* c, const unsigned* a, unsigned b0, unsigned b1) {
    asm volatile("mma.sync.aligned.m16n8k16.row.col.f32.f16.f16.f32 "
                 "{%0,%1,%2,%3}, {%4,%5,%6,%7}, {%8,%9}, {%0,%1,%2,%3};"
                 : "+f"(c[0]), "+f"(c[1]), "+f"(c[2]), "+f"(c[3])
                 : "r"(a[0]), "r"(a[1]), "r"(a[2]), "r"(a[3]), "r"(b0), "r"(b1));
}
__device__ __forceinline__ unsigned packh2(float x, float y) {
    __half2 h = __floats2half2_rn(x, y);
    return *(unsigned*)&h;
}
__device__ __forceinline__ float silu_f(float v) { return v * (1.0f/(1.0f+__expf(-v))); }

__device__ __forceinline__ int act_off(int m, int k) {
    return m*512 + ((((k>>3) ^ (m&7)) << 4) + (k&7)*2);
}
__device__ __forceinline__ int b_off(int n, int kc) {
    return n*128 + ((((kc>>3) ^ (n&7)) << 4) + (kc&7)*2);
}

// ---------------- prep: zero hacc + build fp16 W^T swizzled chunk images ----
__global__ void __launch_bounds__(256) prep_kernel(const float* __restrict__ Wd,
                                                   const float* __restrict__ Ws)
{
    size_t stride = (size_t)gridDim.x * blockDim.x;
    size_t t0 = (size_t)blockIdx.x * blockDim.x + threadIdx.x;
    float4 z = make_float4(0.f,0.f,0.f,0.f);
    for (size_t v = t0; v < (size_t)NNODES*HID/4; v += stride) ((float4*)g_hacc)[v] = z;
    for (size_t e = t0; e < 229376; e += stride) {
        int l, k, n;
        if (e < 32768) { l = 0; k = (int)(e >> 8); n = (int)(e & 255); }
        else { size_t r = e - 32768; l = 1 + (int)(r >> 16); k = (int)((r >> 8) & 255); n = (int)(r & 255); }
        float w = (l == 0) ? Wd[k*256+n] : Ws[(size_t)(l-1)*65536 + k*256 + n];
        int chunk = k >> 6, kc = k & 63;
        int tile = (l == 0) ? chunk : 2 + (l-1)*4 + chunk;
        int dst = n*64 + (((kc>>3) ^ (n&7)) << 3) + (kc&7);
        g_wimg[(size_t)tile*16384 + dst] = __float2half_rn(w);
    }
}

// ---------------- edge stage: scatter-atomic, 4 edges in flight per warp ----
__global__ void __launch_bounds__(256) edge_kernel(
    const float* __restrict__ x, const float* __restrict__ rbf,
    const void* __restrict__ idx, const float* __restrict__ Wr)
{
    __shared__ float Wsh[NRAD * HID];
    __shared__ int s64;
    if (threadIdx.x == 0) {
        int a = 1; const int* p = (const int*)idx;
        for (int k = 1; k < 64; k += 2) a &= (p[k] == 0);
        s64 = a;
    }
    for (int t = threadIdx.x; t < NRAD*HID; t += blockDim.x) Wsh[t] = Wr[t];
    __syncthreads();

    const int is64 = s64;
    const int c = (threadIdx.x & 31) * 4;
    const int warp  = blockIdx.x * 8 + (threadIdx.x >> 5);
    const int nwarp = gridDim.x * 8;

    // hoist the 6x4 weight coefficients for this lane's channel group
    float Wc[4][6];
#pragma unroll
    for (int j = 0; j < 6; j++) {
        Wc[0][j] = Wsh[j*HID + c + 0];
        Wc[1][j] = Wsh[j*HID + c + 1];
        Wc[2][j] = Wsh[j*HID + c + 2];
        Wc[3][j] = Wsh[j*HID + c + 3];
    }

    const int NB = E_NUM / 4;                 // 150000 batches of 4 edges
    for (int b = warp; b < NB; b += nwarp) {
        const int e0 = b * 4;
        long long nd[4];
        float2 q[4][3];
        float4 xv[4];
#pragma unroll
        for (int j = 0; j < 4; j++) {
            nd[j] = is64 ? __ldcs((const long long*)idx + e0 + j)
                         : (long long)__ldcs((const int*)idx + e0 + j);
            const float2* rp2 = (const float2*)(rbf + (size_t)(e0 + j) * NRAD);
            q[j][0] = __ldcs(rp2); q[j][1] = __ldcs(rp2 + 1); q[j][2] = __ldcs(rp2 + 2);
            xv[j] = __ldcs((const float4*)(x + (size_t)(e0 + j)*HID + c));
        }
#pragma unroll
        for (int j = 0; j < 4; j++) {
            float r0 = q[j][0].x, r1 = q[j][0].y, r2 = q[j][1].x,
                  r3 = q[j][1].y, r4 = q[j][2].x, r5 = q[j][2].y;
            float w0 = r0*Wc[0][0]+r1*Wc[0][1]+r2*Wc[0][2]+r3*Wc[0][3]+r4*Wc[0][4]+r5*Wc[0][5];
            float w1 = r0*Wc[1][0]+r1*Wc[1][1]+r2*Wc[1][2]+r3*Wc[1][3]+r4*Wc[1][4]+r5*Wc[1][5];
            float w2 = r0*Wc[2][0]+r1*Wc[2][1]+r2*Wc[2][2]+r3*Wc[2][3]+r4*Wc[2][4]+r5*Wc[2][5];
            float w3 = r0*Wc[3][0]+r1*Wc[3][1]+r2*Wc[3][2]+r3*Wc[3][3]+r4*Wc[3][4]+r5*Wc[3][5];
            float* dst = g_hacc + (size_t)nd[j]*HID + c;
            asm volatile("red.global.add.v4.f32 [%0], {%1,%2,%3,%4};"
                         :: "l"(dst), "f"(w0*xv[j].x), "f"(w1*xv[j].y),
                            "f"(w2*xv[j].z), "f"(w3*xv[j].w) : "memory");
        }
    }
}

// ---------------- MLP on mma.sync fp16 (round-8 form) ----------------
#define SMEM_DYN (32768 + 2*32768)

__global__ void __launch_bounds__(256, 2) mlp_kernel(const float* __restrict__ bs,
                                                     float* __restrict__ out)
{
    extern __shared__ char dsm[];
    char* act = dsm;
    char* bbuf[2] = { dsm + 32768, dsm + 65536 };

    const int tid  = threadIdx.x;
    const int wid  = tid >> 5, lane = tid & 31;
    const int wm   = wid >> 2;
    const int wn   = wid & 3;
    const int gr   = lane >> 2;
    const int gc   = lane & 3;
    const int nodeBase = blockIdx.x * 64;

    {
        int row = tid >> 2;
        int q   = tid & 3;
        int node = nodeBase + row;
        bool ok  = (node < NNODES);
        const float4* src = (const float4*)(g_hacc + (size_t)node * HID);
#pragma unroll
        for (int w4 = 0; w4 < 8; w4++) {
            int k0 = q*32 + w4*4;
            float4 v = ok ? __ldcs(&src[k0 >> 2]) : make_float4(0.f,0.f,0.f,0.f);
            *(unsigned*)(act + act_off(row, k0))     = packh2(v.x, v.y);
            *(unsigned*)(act + act_off(row, k0 + 2)) = packh2(v.z, v.w);
        }
    }
    __syncthreads();

    for (int l = 0; l < 4; l++) {
        const int nch   = (l == 0) ? 2 : 4;
        const int tbase = (l == 0) ? 0 : 2 + (l-1)*4;

        float C[2][8][4];
#pragma unroll
        for (int i=0;i<2;i++)
#pragma unroll
            for (int j=0;j<8;j++) { C[i][j][0]=0.f; C[i][j][1]=0.f; C[i][j][2]=0.f; C[i][j][3]=0.f; }

        {
            const char* src = (const char*)(g_wimg + (size_t)tbase*16384) + tid*16;
#pragma unroll
            for (int q = 0; q < 8; q++) cpa16(bbuf[0] + tid*16 + q*4096, src + q*4096);
            CP_COMMIT();
        }

        for (int c = 0; c < nch; c++) {
            const int b = c & 1;
            if (c + 1 < nch) {
                const char* src = (const char*)(g_wimg + (size_t)(tbase+c+1)*16384) + tid*16;
#pragma unroll
                for (int q = 0; q < 8; q++) cpa16(bbuf[b^1] + tid*16 + q*4096, src + q*4096);
                CP_COMMIT();
                CP_WAIT1();
            } else CP_WAIT0();
            __syncthreads();

            const char* bb = bbuf[b];
#pragma unroll
            for (int kk = 0; kk < 4; kk++) {
                const int kb = c*64 + kk*16;
                const int kc = kk*16;
                unsigned a[2][4];
#pragma unroll
                for (int i = 0; i < 2; i++) {
                    int m = wm*32 + i*16 + gr;
                    a[i][0] = *(const unsigned*)(act + act_off(m,     kb     + gc*2));
                    a[i][1] = *(const unsigned*)(act + act_off(m + 8, kb     + gc*2));
                    a[i][2] = *(const unsigned*)(act + act_off(m,     kb + 8 + gc*2));
                    a[i][3] = *(const unsigned*)(act + act_off(m + 8, kb + 8 + gc*2));
                }
#pragma unroll
                for (int j = 0; j < 8; j++) {
                    int n = wn*64 + j*8 + gr;
                    unsigned b0 = *(const unsigned*)(bb + b_off(n, kc     + gc*2));
                    unsigned b1 = *(const unsigned*)(bb + b_off(n, kc + 8 + gc*2));
#pragma unroll
                    for (int i = 0; i < 2; i++) mma16816(C[i][j], a[i], b0, b1);
                }
            }
            __syncthreads();
        }

        if (l < 3) {
#pragma unroll
            for (int i = 0; i < 2; i++) {
                int r0 = wm*32 + i*16 + gr;
#pragma unroll
                for (int j = 0; j < 8; j++) {
                    int n0 = wn*64 + j*8 + gc*2;
                    float v00=C[i][j][0], v01=C[i][j][1], v10=C[i][j][2], v11=C[i][j][3];
                    if (l > 0) {
                        float b0 = __ldg(bs + (l-1)*256 + n0), b1 = __ldg(bs + (l-1)*256 + n0 + 1);
                        v00 = silu_f(v00 + b0); v01 = silu_f(v01 + b1);
                        v10 = silu_f(v10 + b0); v11 = silu_f(v11 + b1);
                    }
                    *(unsigned*)(act + act_off(r0,     n0)) = packh2(v00, v01);
                    *(unsigned*)(act + act_off(r0 + 8, n0)) = packh2(v10, v11);
                }
            }
            __syncthreads();
        } else {
#pragma unroll
            for (int i = 0; i < 2; i++) {
                int r0 = wm*32 + i*16 + gr;
                long long node0 = nodeBase + r0, node1 = node0 + 8;
#pragma unroll
                for (int j = 0; j < 8; j++) {
                    int n0 = wn*64 + j*8 + gc*2;
                    float b0 = __ldg(bs + 512 + n0), b1 = __ldg(bs + 512 + n0 + 1);
                    if (node0 < NNODES) {
                        float* op = out + (size_t)node0*256 + n0;
                        op[0] = silu_f(C[i][j][0] + b0);
                        op[1] = silu_f(C[i][j][1] + b1);
                    }
                    if (node1 < NNODES) {
                        float* op = out + (size_t)node1*256 + n0;
                        op[0] = silu_f(C[i][j][2] + b0);
                        op[1] = silu_f(C[i][j][3] + b1);
                    }
                }
            }
        }
    }
}

// ---------------------------------------------------------------------------
extern "C" void kernel_launch(void* const* d_in, const int* in_sizes, int n_in,
                              void* d_out, int out_size)
{
    const float* x      = (const float*)d_in[0];
    const float* rbf    = (const float*)d_in[1];
    const void*  idx    = d_in[2];
    const float* W_rbf  = (const float*)d_in[3];
    const float* W_down = (const float*)d_in[4];
    const float* Ws     = (const float*)d_in[5];
    const float* bs     = (const float*)d_in[6];
    float* out = (float*)d_out;

    prep_kernel<<<448, 256>>>(W_down, Ws);
    edge_kernel<<<1184, 256>>>(x, rbf, idx, W_rbf);
    cudaFuncSetAttribute(mlp_kernel, cudaFuncAttributeMaxDynamicSharedMemorySize, SMEM_DYN);
    mlp_kernel<<<NT, 256, SMEM_DYN>>>(bs, out);
}

// round 14
// speedup vs baseline: 1.8305x; 1.3140x over previous
#include <cuda_runtime.h>
#include <cuda_fp16.h>
#include <math.h>

#define E_NUM   600000
#define NRAD    6
#define HID     128
#define NNODES  50000
#define NT      782          // 64-node MLP tiles

__device__ float g_hacc[(size_t)NNODES * HID];
__device__ __align__(256) __half g_wimg[14 * 16384];   // fp16 W^T swizzled chunk images

// ---------------- helpers ----------------
__device__ __forceinline__ void cpa16(void* dst, const void* src) {
    unsigned d = (unsigned)__cvta_generic_to_shared(dst);
    asm volatile("cp.async.cg.shared.global [%0], [%1], 16;" :: "r"(d), "l"(src));
}
#define CP_COMMIT() asm volatile("cp.async.commit_group;" ::: "memory")
#define CP_WAIT1()  asm volatile("cp.async.wait_group 1;" ::: "memory")
#define CP_WAIT0()  asm volatile("cp.async.wait_group 0;" ::: "memory")

__device__ __forceinline__ void mma16816(float* c, const unsigned* a, unsigned b0, unsigned b1) {
    asm volatile("mma.sync.aligned.m16n8k16.row.col.f32.f16.f16.f32 "
                 "{%0,%1,%2,%3}, {%4,%5,%6,%7}, {%8,%9}, {%0,%1,%2,%3};"
                 : "+f"(c[0]), "+f"(c[1]), "+f"(c[2]), "+f"(c[3])
                 : "r"(a[0]), "r"(a[1]), "r"(a[2]), "r"(a[3]), "r"(b0), "r"(b1));
}
__device__ __forceinline__ unsigned packh2(float x, float y) {
    __half2 h = __floats2half2_rn(x, y);
    return *(unsigned*)&h;
}
__device__ __forceinline__ float silu_f(float v) { return v * (1.0f/(1.0f+__expf(-v))); }

__device__ __forceinline__ int act_off(int m, int k) {
    return m*512 + ((((k>>3) ^ (m&7)) << 4) + (k&7)*2);
}
__device__ __forceinline__ int b_off(int n, int kc) {
    return n*128 + ((((kc>>3) ^ (n&7)) << 4) + (kc&7)*2);
}

// ---------------- prep: zero hacc + build fp16 W^T swizzled chunk images ----
__global__ void __launch_bounds__(256) prep_kernel(const float* __restrict__ Wd,
                                                   const float* __restrict__ Ws)
{
    size_t stride = (size_t)gridDim.x * blockDim.x;
    size_t t0 = (size_t)blockIdx.x * blockDim.x + threadIdx.x;
    float4 z = make_float4(0.f,0.f,0.f,0.f);
    for (size_t v = t0; v < (size_t)NNODES*HID/4; v += stride) ((float4*)g_hacc)[v] = z;
    for (size_t e = t0; e < 229376; e += stride) {
        int l, k, n;
        if (e < 32768) { l = 0; k = (int)(e >> 8); n = (int)(e & 255); }
        else { size_t r = e - 32768; l = 1 + (int)(r >> 16); k = (int)((r >> 8) & 255); n = (int)(r & 255); }
        float w = (l == 0) ? Wd[k*256+n] : Ws[(size_t)(l-1)*65536 + k*256 + n];
        int chunk = k >> 6, kc = k & 63;
        int tile = (l == 0) ? chunk : 2 + (l-1)*4 + chunk;
        int dst = n*64 + (((kc>>3) ^ (n&7)) << 3) + (kc&7);
        g_wimg[(size_t)tile*16384 + dst] = __float2half_rn(w);
    }
}

// ---------------- edge stage: pair-packed loads, 128-thr blocks ----------------
__global__ void __launch_bounds__(128, 8) edge_kernel(
    const float* __restrict__ x, const float* __restrict__ rbf,
    const void* __restrict__ idx, const float* __restrict__ Wr)
{
    __shared__ float Wsh[NRAD * HID];
    __shared__ int s64;
    if (threadIdx.x == 0) {
        int a = 1; const int* p = (const int*)idx;
        for (int k = 1; k < 64; k += 2) a &= (p[k] == 0);
        s64 = a;
    }
    for (int t = threadIdx.x; t < NRAD*HID; t += blockDim.x) Wsh[t] = Wr[t];
    __syncthreads();

    const int is64 = s64;
    const int c = (threadIdx.x & 31) * 4;
    const int warp  = blockIdx.x * 4 + (threadIdx.x >> 5);
    const int nwarp = gridDim.x * 4;

    float Wc[4][6];
#pragma unroll
    for (int j = 0; j < 6; j++) {
        Wc[0][j] = Wsh[j*HID + c + 0];
        Wc[1][j] = Wsh[j*HID + c + 1];
        Wc[2][j] = Wsh[j*HID + c + 2];
        Wc[3][j] = Wsh[j*HID + c + 3];
    }

    const int NP = E_NUM / 2;             // 300000 edge pairs
    for (int p = warp; p < NP; p += nwarp) {
        const int e0 = p * 2;
        long long n0, n1;
        if (is64) {
            longlong2 ii = __ldcs((const longlong2*)idx + p);
            n0 = ii.x; n1 = ii.y;
        } else {
            int2 ii = __ldcs((const int2*)idx + p);
            n0 = ii.x; n1 = ii.y;
        }
        const float4* rp = (const float4*)(rbf + (size_t)e0 * NRAD);   // 48B, 16B-aligned
        float4 v0 = __ldcs(rp), v1 = __ldcs(rp + 1), v2 = __ldcs(rp + 2);
        float4 x0 = __ldcs((const float4*)(x + (size_t)e0*HID + c));
        float4 x1 = __ldcs((const float4*)(x + (size_t)(e0+1)*HID + c));

        // edge 0: rbf = v0.x v0.y v0.z v0.w v1.x v1.y
        {
            float w0 = v0.x*Wc[0][0]+v0.y*Wc[0][1]+v0.z*Wc[0][2]+v0.w*Wc[0][3]+v1.x*Wc[0][4]+v1.y*Wc[0][5];
            float w1 = v0.x*Wc[1][0]+v0.y*Wc[1][1]+v0.z*Wc[1][2]+v0.w*Wc[1][3]+v1.x*Wc[1][4]+v1.y*Wc[1][5];
            float w2 = v0.x*Wc[2][0]+v0.y*Wc[2][1]+v0.z*Wc[2][2]+v0.w*Wc[2][3]+v1.x*Wc[2][4]+v1.y*Wc[2][5];
            float w3 = v0.x*Wc[3][0]+v0.y*Wc[3][1]+v0.z*Wc[3][2]+v0.w*Wc[3][3]+v1.x*Wc[3][4]+v1.y*Wc[3][5];
            float* dst = g_hacc + (size_t)n0*HID + c;
            asm volatile("red.global.add.v4.f32 [%0], {%1,%2,%3,%4};"
                         :: "l"(dst), "f"(w0*x0.x), "f"(w1*x0.y), "f"(w2*x0.z), "f"(w3*x0.w) : "memory");
        }
        // edge 1: rbf = v1.z v1.w v2.x v2.y v2.z v2.w
        {
            float w0 = v1.z*Wc[0][0]+v1.w*Wc[0][1]+v2.x*Wc[0][2]+v2.y*Wc[0][3]+v2.z*Wc[0][4]+v2.w*Wc[0][5];
            float w1 = v1.z*Wc[1][0]+v1.w*Wc[1][1]+v2.x*Wc[1][2]+v2.y*Wc[1][3]+v2.z*Wc[1][4]+v2.w*Wc[1][5];
            float w2 = v1.z*Wc[2][0]+v1.w*Wc[2][1]+v2.x*Wc[2][2]+v2.y*Wc[2][3]+v2.z*Wc[2][4]+v2.w*Wc[2][5];
            float w3 = v1.z*Wc[3][0]+v1.w*Wc[3][1]+v2.x*Wc[3][2]+v2.y*Wc[3][3]+v2.z*Wc[3][4]+v2.w*Wc[3][5];
            float* dst = g_hacc + (size_t)n1*HID + c;
            asm volatile("red.global.add.v4.f32 [%0], {%1,%2,%3,%4};"
                         :: "l"(dst), "f"(w0*x1.x), "f"(w1*x1.y), "f"(w2*x1.z), "f"(w3*x1.w) : "memory");
        }
    }
}

// ---------------- MLP on mma.sync fp16 (round-8 form) ----------------
#define SMEM_DYN (32768 + 2*32768)

__global__ void __launch_bounds__(256, 2) mlp_kernel(const float* __restrict__ bs,
                                                     float* __restrict__ out)
{
    extern __shared__ char dsm[];
    char* act = dsm;
    char* bbuf[2] = { dsm + 32768, dsm + 65536 };

    const int tid  = threadIdx.x;
    const int wid  = tid >> 5, lane = tid & 31;
    const int wm   = wid >> 2;
    const int wn   = wid & 3;
    const int gr   = lane >> 2;
    const int gc   = lane & 3;
    const int nodeBase = blockIdx.x * 64;

    {
        int row = tid >> 2;
        int q   = tid & 3;
        int node = nodeBase + row;
        bool ok  = (node < NNODES);
        const float4* src = (const float4*)(g_hacc + (size_t)node * HID);
#pragma unroll
        for (int w4 = 0; w4 < 8; w4++) {
            int k0 = q*32 + w4*4;
            float4 v = ok ? __ldcs(&src[k0 >> 2]) : make_float4(0.f,0.f,0.f,0.f);
            *(unsigned*)(act + act_off(row, k0))     = packh2(v.x, v.y);
            *(unsigned*)(act + act_off(row, k0 + 2)) = packh2(v.z, v.w);
        }
    }
    __syncthreads();

    for (int l = 0; l < 4; l++) {
        const int nch   = (l == 0) ? 2 : 4;
        const int tbase = (l == 0) ? 0 : 2 + (l-1)*4;

        float C[2][8][4];
#pragma unroll
        for (int i=0;i<2;i++)
#pragma unroll
            for (int j=0;j<8;j++) { C[i][j][0]=0.f; C[i][j][1]=0.f; C[i][j][2]=0.f; C[i][j][3]=0.f; }

        {
            const char* src = (const char*)(g_wimg + (size_t)tbase*16384) + tid*16;
#pragma unroll
            for (int q = 0; q < 8; q++) cpa16(bbuf[0] + tid*16 + q*4096, src + q*4096);
            CP_COMMIT();
        }

        for (int c = 0; c < nch; c++) {
            const int b = c & 1;
            if (c + 1 < nch) {
                const char* src = (const char*)(g_wimg + (size_t)(tbase+c+1)*16384) + tid*16;
#pragma unroll
                for (int q = 0; q < 8; q++) cpa16(bbuf[b^1] + tid*16 + q*4096, src + q*4096);
                CP_COMMIT();
                CP_WAIT1();
            } else CP_WAIT0();
            __syncthreads();

            const char* bb = bbuf[b];
#pragma unroll
            for (int kk = 0; kk < 4; kk++) {
                const int kb = c*64 + kk*16;
                const int kc = kk*16;
                unsigned a[2][4];
#pragma unroll
                for (int i = 0; i < 2; i++) {
                    int m = wm*32 + i*16 + gr;
                    a[i][0] = *(const unsigned*)(act + act_off(m,     kb     + gc*2));
                    a[i][1] = *(const unsigned*)(act + act_off(m + 8, kb     + gc*2));
                    a[i][2] = *(const unsigned*)(act + act_off(m,     kb + 8 + gc*2));
                    a[i][3] = *(const unsigned*)(act + act_off(m + 8, kb + 8 + gc*2));
                }
#pragma unroll
                for (int j = 0; j < 8; j++) {
                    int n = wn*64 + j*8 + gr;
                    unsigned b0 = *(const unsigned*)(bb + b_off(n, kc     + gc*2));
                    unsigned b1 = *(const unsigned*)(bb + b_off(n, kc + 8 + gc*2));
#pragma unroll
                    for (int i = 0; i < 2; i++) mma16816(C[i][j], a[i], b0, b1);
                }
            }
            __syncthreads();
        }

        if (l < 3) {
#pragma unroll
            for (int i = 0; i < 2; i++) {
                int r0 = wm*32 + i*16 + gr;
#pragma unroll
                for (int j = 0; j < 8; j++) {
                    int n0 = wn*64 + j*8 + gc*2;
                    float v00=C[i][j][0], v01=C[i][j][1], v10=C[i][j][2], v11=C[i][j][3];
                    if (l > 0) {
                        float b0 = __ldg(bs + (l-1)*256 + n0), b1 = __ldg(bs + (l-1)*256 + n0 + 1);
                        v00 = silu_f(v00 + b0); v01 = silu_f(v01 + b1);
                        v10 = silu_f(v10 + b0); v11 = silu_f(v11 + b1);
                    }
                    *(unsigned*)(act + act_off(r0,     n0)) = packh2(v00, v01);
                    *(unsigned*)(act + act_off(r0 + 8, n0)) = packh2(v10, v11);
                }
            }
            __syncthreads();
        } else {
#pragma unroll
            for (int i = 0; i < 2; i++) {
                int r0 = wm*32 + i*16 + gr;
                long long node0 = nodeBase + r0, node1 = node0 + 8;
#pragma unroll
                for (int j = 0; j < 8; j++) {
                    int n0 = wn*64 + j*8 + gc*2;
                    float b0 = __ldg(bs + 512 + n0), b1 = __ldg(bs + 512 + n0 + 1);
                    if (node0 < NNODES) {
                        float* op = out + (size_t)node0*256 + n0;
                        op[0] = silu_f(C[i][j][0] + b0);
                        op[1] = silu_f(C[i][j][1] + b1);
                    }
                    if (node1 < NNODES) {
                        float* op = out + (size_t)node1*256 + n0;
                        op[0] = silu_f(C[i][j][2] + b0);
                        op[1] = silu_f(C[i][j][3] + b1);
                    }
                }
            }
        }
    }
}

// ---------------------------------------------------------------------------
extern "C" void kernel_launch(void* const* d_in, const int* in_sizes, int n_in,
                              void* d_out, int out_size)
{
    const float* x      = (const float*)d_in[0];
    const float* rbf    = (const float*)d_in[1];
    const void*  idx    = d_in[2];
    const float* W_rbf  = (const float*)d_in[3];
    const float* W_down = (const float*)d_in[4];
    const float* Ws     = (const float*)d_in[5];
    const float* bs     = (const float*)d_in[6];
    float* out = (float*)d_out;

    prep_kernel<<<448, 256>>>(W_down, Ws);
    edge_kernel<<<2368, 128>>>(x, rbf, idx, W_rbf);
    cudaFuncSetAttribute(mlp_kernel, cudaFuncAttributeMaxDynamicSharedMemorySize, SMEM_DYN);
    mlp_kernel<<<NT, 256, SMEM_DYN>>>(bs, out);
}

// round 17
// speedup vs baseline: 1.9599x; 1.0707x over previous
#include <cuda_runtime.h>
#include <cuda_fp16.h>
#include <math.h>

#define E_NUM   600000
#define NRAD    6
#define HID     128
#define NNODES  50000
#define NT      782          // 64-node MLP tiles

__device__ float g_hacc[(size_t)NNODES * HID];
__device__ __align__(256) __half g_wimg[14 * 16384];   // fp16 W^T swizzled chunk images

// ---------------- helpers ----------------
__device__ __forceinline__ void cpa16(void* dst, const void* src) {
    unsigned d = (unsigned)__cvta_generic_to_shared(dst);
    asm volatile("cp.async.cg.shared.global [%0], [%1], 16;" :: "r"(d), "l"(src));
}
#define CP_COMMIT() asm volatile("cp.async.commit_group;" ::: "memory")
#define CP_WAIT1()  asm volatile("cp.async.wait_group 1;" ::: "memory")
#define CP_WAIT0()  asm volatile("cp.async.wait_group 0;" ::: "memory")

__device__ __forceinline__ void mma16816(float* c, const unsigned* a, unsigned b0, unsigned b1) {
    asm volatile("mma.sync.aligned.m16n8k16.row.col.f32.f16.f16.f32 "
                 "{%0,%1,%2,%3}, {%4,%5,%6,%7}, {%8,%9}, {%0,%1,%2,%3};"
                 : "+f"(c[0]), "+f"(c[1]), "+f"(c[2]), "+f"(c[3])
                 : "r"(a[0]), "r"(a[1]), "r"(a[2]), "r"(a[3]), "r"(b0), "r"(b1));
}
__device__ __forceinline__ void ldsm4(unsigned* r, unsigned addr) {
    asm volatile("ldmatrix.sync.aligned.m8n8.x4.shared.b16 {%0,%1,%2,%3}, [%4];"
                 : "=r"(r[0]), "=r"(r[1]), "=r"(r[2]), "=r"(r[3]) : "r"(addr));
}
__device__ __forceinline__ unsigned packh2(float x, float y) {
    __half2 h = __floats2half2_rn(x, y);
    return *(unsigned*)&h;
}
__device__ __forceinline__ float silu_f(float v) { return v * (1.0f/(1.0f+__expf(-v))); }

__device__ __forceinline__ int act_off(int m, int k) {
    return m*512 + ((((k>>3) ^ (m&7)) << 4) + (k&7)*2);
}
__device__ __forceinline__ int b_off(int n, int kc) {
    return n*128 + ((((kc>>3) ^ (n&7)) << 4) + (kc&7)*2);
}

// ---------------- prep: zero hacc + build fp16 W^T swizzled chunk images ----
__global__ void __launch_bounds__(256) prep_kernel(const float* __restrict__ Wd,
                                                   const float* __restrict__ Ws)
{
    size_t stride = (size_t)gridDim.x * blockDim.x;
    size_t t0 = (size_t)blockIdx.x * blockDim.x + threadIdx.x;
    float4 z = make_float4(0.f,0.f,0.f,0.f);
    for (size_t v = t0; v < (size_t)NNODES*HID/4; v += stride) ((float4*)g_hacc)[v] = z;
    for (size_t e = t0; e < 229376; e += stride) {
        int l, k, n;
        if (e < 32768) { l = 0; k = (int)(e >> 8); n = (int)(e & 255); }
        else { size_t r = e - 32768; l = 1 + (int)(r >> 16); k = (int)((r >> 8) & 255); n = (int)(r & 255); }
        float w = (l == 0) ? Wd[k*256+n] : Ws[(size_t)(l-1)*65536 + k*256 + n];
        int chunk = k >> 6, kc = k & 63;
        int tile = (l == 0) ? chunk : 2 + (l-1)*4 + chunk;
        int dst = n*64 + (((kc>>3) ^ (n&7)) << 3) + (kc&7);
        g_wimg[(size_t)tile*16384 + dst] = __float2half_rn(w);
    }
}

// ---------------- edge stage: pair-packed loads, 128-thr blocks ----------------
__global__ void __launch_bounds__(128, 8) edge_kernel(
    const float* __restrict__ x, const float* __restrict__ rbf,
    const void* __restrict__ idx, const float* __restrict__ Wr)
{
    __shared__ float Wsh[NRAD * HID];
    __shared__ int s64;
    if (threadIdx.x == 0) {
        int a = 1; const int* p = (const int*)idx;
        for (int k = 1; k < 64; k += 2) a &= (p[k] == 0);
        s64 = a;
    }
    for (int t = threadIdx.x; t < NRAD*HID; t += blockDim.x) Wsh[t] = Wr[t];
    __syncthreads();

    const int is64 = s64;
    const int c = (threadIdx.x & 31) * 4;
    const int warp  = blockIdx.x * 4 + (threadIdx.x >> 5);
    const int nwarp = gridDim.x * 4;

    float Wc[4][6];
#pragma unroll
    for (int j = 0; j < 6; j++) {
        Wc[0][j] = Wsh[j*HID + c + 0];
        Wc[1][j] = Wsh[j*HID + c + 1];
        Wc[2][j] = Wsh[j*HID + c + 2];
        Wc[3][j] = Wsh[j*HID + c + 3];
    }

    const int NP = E_NUM / 2;             // 300000 edge pairs
    for (int p = warp; p < NP; p += nwarp) {
        const int e0 = p * 2;
        long long n0, n1;
        if (is64) {
            longlong2 ii = __ldcs((const longlong2*)idx + p);
            n0 = ii.x; n1 = ii.y;
        } else {
            int2 ii = __ldcs((const int2*)idx + p);
            n0 = ii.x; n1 = ii.y;
        }
        const float4* rp = (const float4*)(rbf + (size_t)e0 * NRAD);   // 48B, 16B-aligned
        float4 v0 = __ldcs(rp), v1 = __ldcs(rp + 1), v2 = __ldcs(rp + 2);
        float4 x0 = __ldcs((const float4*)(x + (size_t)e0*HID + c));
        float4 x1 = __ldcs((const float4*)(x + (size_t)(e0+1)*HID + c));

        {
            float w0 = v0.x*Wc[0][0]+v0.y*Wc[0][1]+v0.z*Wc[0][2]+v0.w*Wc[0][3]+v1.x*Wc[0][4]+v1.y*Wc[0][5];
            float w1 = v0.x*Wc[1][0]+v0.y*Wc[1][1]+v0.z*Wc[1][2]+v0.w*Wc[1][3]+v1.x*Wc[1][4]+v1.y*Wc[1][5];
            float w2 = v0.x*Wc[2][0]+v0.y*Wc[2][1]+v0.z*Wc[2][2]+v0.w*Wc[2][3]+v1.x*Wc[2][4]+v1.y*Wc[2][5];
            float w3 = v0.x*Wc[3][0]+v0.y*Wc[3][1]+v0.z*Wc[3][2]+v0.w*Wc[3][3]+v1.x*Wc[3][4]+v1.y*Wc[3][5];
            float* dst = g_hacc + (size_t)n0*HID + c;
            asm volatile("red.global.add.v4.f32 [%0], {%1,%2,%3,%4};"
                         :: "l"(dst), "f"(w0*x0.x), "f"(w1*x0.y), "f"(w2*x0.z), "f"(w3*x0.w) : "memory");
        }
        {
            float w0 = v1.z*Wc[0][0]+v1.w*Wc[0][1]+v2.x*Wc[0][2]+v2.y*Wc[0][3]+v2.z*Wc[0][4]+v2.w*Wc[0][5];
            float w1 = v1.z*Wc[1][0]+v1.w*Wc[1][1]+v2.x*Wc[1][2]+v2.y*Wc[1][3]+v2.z*Wc[1][4]+v2.w*Wc[1][5];
            float w2 = v1.z*Wc[2][0]+v1.w*Wc[2][1]+v2.x*Wc[2][2]+v2.y*Wc[2][3]+v2.z*Wc[2][4]+v2.w*Wc[2][5];
            float w3 = v1.z*Wc[3][0]+v1.w*Wc[3][1]+v2.x*Wc[3][2]+v2.y*Wc[3][3]+v2.z*Wc[3][4]+v2.w*Wc[3][5];
            float* dst = g_hacc + (size_t)n1*HID + c;
            asm volatile("red.global.add.v4.f32 [%0], {%1,%2,%3,%4};"
                         :: "l"(dst), "f"(w0*x1.x), "f"(w1*x1.y), "f"(w2*x1.z), "f"(w3*x1.w) : "memory");
        }
    }
}

// ---------------- MLP on mma.sync fp16 + ldmatrix ----------------
#define SMEM_DYN (32768 + 2*32768)

__global__ void __launch_bounds__(256, 2) mlp_kernel(const float* __restrict__ bs,
                                                     float* __restrict__ out)
{
    extern __shared__ char dsm[];
    char* act = dsm;
    char* bbuf[2] = { dsm + 32768, dsm + 65536 };
    const unsigned act_u  = (unsigned)__cvta_generic_to_shared(act);
    const unsigned bbuf_u[2] = { (unsigned)__cvta_generic_to_shared(bbuf[0]),
                                 (unsigned)__cvta_generic_to_shared(bbuf[1]) };

    const int tid  = threadIdx.x;
    const int wid  = tid >> 5, lane = tid & 31;
    const int wm   = wid >> 2;
    const int wn   = wid & 3;
    const int gr   = lane >> 2;
    const int gc   = lane & 3;
    const int nodeBase = blockIdx.x * 64;

    // ldmatrix per-lane base offsets (XOR-linear in fragment-aligned k)
    // A (i=0,1): matrices: lanes0-7 rows m0..m0+7 kh=0; 8-15 rows+8 kh=0; 16-23 rows kh=8; 24-31 rows+8 kh=8
    unsigned Ab[2];
    {
        int lt = lane & 7, lh = (lane >> 3) & 1, lq = lane >> 4;
#pragma unroll
        for (int i = 0; i < 2; i++) {
            int row = wm*32 + i*16 + lh*8 + lt;
            Ab[i] = (unsigned)(row*512 + ((row & 7) << 4)) ^ (unsigned)(lq << 4);
        }
    }
    // B (q=0..3): matrix t = lane>>3: j = 2q + (t>>1), kh = (t&1)*8, row n = wn*64 + j*8 + (lane&7)
    unsigned Bb[4];
    {
        int lt = lane & 7, t = lane >> 3;
#pragma unroll
        for (int q = 0; q < 4; q++) {
            int n = wn*64 + (2*q + (t >> 1))*8 + lt;
            Bb[q] = (unsigned)(n*128 + ((n & 7) << 4)) ^ (unsigned)((t & 1) << 4);
        }
    }

    // ---- stage layer-0 A: hacc fp32 -> fp16 swizzled act (cols 0..127)
    {
        int row = tid >> 2;
        int q   = tid & 3;
        int node = nodeBase + row;
        bool ok  = (node < NNODES);
        const float4* src = (const float4*)(g_hacc + (size_t)node * HID);
#pragma unroll
        for (int w4 = 0; w4 < 8; w4++) {
            int k0 = q*32 + w4*4;
            float4 v = ok ? __ldcs(&src[k0 >> 2]) : make_float4(0.f,0.f,0.f,0.f);
            *(unsigned*)(act + act_off(row, k0))     = packh2(v.x, v.y);
            *(unsigned*)(act + act_off(row, k0 + 2)) = packh2(v.z, v.w);
        }
    }
    __syncthreads();

    for (int l = 0; l < 4; l++) {
        const int nch   = (l == 0) ? 2 : 4;
        const int tbase = (l == 0) ? 0 : 2 + (l-1)*4;

        float C[2][8][4];
#pragma unroll
        for (int i=0;i<2;i++)
#pragma unroll
            for (int j=0;j<8;j++) { C[i][j][0]=0.f; C[i][j][1]=0.f; C[i][j][2]=0.f; C[i][j][3]=0.f; }

        {
            const char* src = (const char*)(g_wimg + (size_t)tbase*16384) + tid*16;
#pragma unroll
            for (int q = 0; q < 8; q++) cpa16(bbuf[0] + tid*16 + q*4096, src + q*4096);
            CP_COMMIT();
        }

        for (int c = 0; c < nch; c++) {
            const int b = c & 1;
            if (c + 1 < nch) {
                const char* src = (const char*)(g_wimg + (size_t)(tbase+c+1)*16384) + tid*16;
#pragma unroll
                for (int q = 0; q < 8; q++) cpa16(bbuf[b^1] + tid*16 + q*4096, src + q*4096);
                CP_COMMIT();
                CP_WAIT1();
            } else CP_WAIT0();
            __syncthreads();

            const unsigned bu = bbuf_u[b];
#pragma unroll
            for (int kk = 0; kk < 4; kk++) {
                const unsigned axor = (unsigned)(c*128 + kk*32);   // ((c*64+kk*16)>>3)<<4
                const unsigned bxor = (unsigned)(kk*32);           // ((kk*16)>>3)<<4
                unsigned a[2][4], bm[4][4];
#pragma unroll
                for (int i = 0; i < 2; i++) ldsm4(a[i], act_u + (Ab[i] ^ axor));
#pragma unroll
                for (int q = 0; q < 4; q++) ldsm4(bm[q], bu + (Bb[q] ^ bxor));
#pragma unroll
                for (int q = 0; q < 4; q++) {
#pragma unroll
                    for (int i = 0; i < 2; i++) {
                        mma16816(C[i][2*q],   a[i], bm[q][0], bm[q][1]);
                        mma16816(C[i][2*q+1], a[i], bm[q][2], bm[q][3]);
                    }
                }
            }
            __syncthreads();
        }

        if (l < 3) {
#pragma unroll
            for (int i = 0; i < 2; i++) {
                int r0 = wm*32 + i*16 + gr;
#pragma unroll
                for (int j = 0; j < 8; j++) {
                    int n0 = wn*64 + j*8 + gc*2;
                    float v00=C[i][j][0], v01=C[i][j][1], v10=C[i][j][2], v11=C[i][j][3];
                    if (l > 0) {
                        float b0 = __ldg(bs + (l-1)*256 + n0), b1 = __ldg(bs + (l-1)*256 + n0 + 1);
                        v00 = silu_f(v00 + b0); v01 = silu_f(v01 + b1);
                        v10 = silu_f(v10 + b0); v11 = silu_f(v11 + b1);
                    }
                    *(unsigned*)(act + act_off(r0,     n0)) = packh2(v00, v01);
                    *(unsigned*)(act + act_off(r0 + 8, n0)) = packh2(v10, v11);
                }
            }
            __syncthreads();
        } else {
#pragma unroll
            for (int i = 0; i < 2; i++) {
                int r0 = wm*32 + i*16 + gr;
                long long node0 = nodeBase + r0, node1 = node0 + 8;
#pragma unroll
                for (int j = 0; j < 8; j++) {
                    int n0 = wn*64 + j*8 + gc*2;
                    float b0 = __ldg(bs + 512 + n0), b1 = __ldg(bs + 512 + n0 + 1);
                    if (node0 < NNODES) {
                        float* op = out + (size_t)node0*256 + n0;
                        op[0] = silu_f(C[i][j][0] + b0);
                        op[1] = silu_f(C[i][j][1] + b1);
                    }
                    if (node1 < NNODES) {
                        float* op = out + (size_t)node1*256 + n0;
                        op[0] = silu_f(C[i][j][2] + b0);
                        op[1] = silu_f(C[i][j][3] + b1);
                    }
                }
            }
        }
    }
}

// ---------------------------------------------------------------------------
extern "C" void kernel_launch(void* const* d_in, const int* in_sizes, int n_in,
                              void* d_out, int out_size)
{
    const float* x      = (const float*)d_in[0];
    const float* rbf    = (const float*)d_in[1];
    const void*  idx    = d_in[2];
    const float* W_rbf  = (const float*)d_in[3];
    const float* W_down = (const float*)d_in[4];
    const float* Ws     = (const float*)d_in[5];
    const float* bs     = (const float*)d_in[6];
    float* out = (float*)d_out;

    prep_kernel<<<1184, 256>>>(W_down, Ws);
    edge_kernel<<<2368, 128>>>(x, rbf, idx, W_rbf);
    cudaFuncSetAttribute(mlp_kernel, cudaFuncAttributeMaxDynamicSharedMemorySize, SMEM_DYN);
    mlp_kernel<<<NT, 256, SMEM_DYN>>>(bs, out);
}